// round 5
// baseline (speedup 1.0000x reference)
#include <cuda_runtime.h>

// Problem constants
#define B_DIM 8
#define D_DIM 40
#define H_DIM 32
#define W_DIM 88
#define C_DIM 80
#define QUADS (C_DIM / 4)        // 20 channel quads
#define NX 256
#define NY 256
#define NCELL (NX * NY)          // 65536 cells per batch
// NZ = 1

// Quad-major scratch accumulator: (B, QUADS, NCELL, 4) fp32 = 168 MB.
// .bss zero-init at module load; reshape_zero restores it to zero each call,
// so it is zero at the start of every kernel_launch call / graph replay.
__device__ float g_scratch[(long long)B_DIM * QUADS * NCELL * 4];

// ---------------------------------------------------------------------------
// Scatter: one block per (b, d, h) row of W=88 points.
// Phase 1: threads 0..87 compute the flat cell index (or -1) into smem.
// Phase 2: loop over (channel-quad q, w): 4 coalesced evict-first x loads,
//          one red.global.add.v4.f32 into scratch[b][q][flat][0..3].
// ---------------------------------------------------------------------------
__global__ void __launch_bounds__(256) scatter_kernel(
    const float* __restrict__ geom,   // (B, D, H, W, 3)
    const float* __restrict__ x)      // (B, D, C, H, W)
{
    __shared__ int s_flat[W_DIM];

    const int bid = blockIdx.x;           // 0 .. B*D*H-1
    const int h   = bid % H_DIM;
    const int bd  = bid / H_DIM;
    const int d   = bd % D_DIM;
    const int b   = bd / D_DIM;

    const int t = threadIdx.x;

    if (t < W_DIM) {
        const float* g = geom + ((long long)bid * W_DIM + t) * 3;
        const float gx = g[0];
        const float gy = g[1];
        const float gz = g[2];

        int flat = -1;
        if (gx >= -51.2f && gx < 51.2f &&
            gy >= -51.2f && gy < 51.2f &&
            gz >= -10.0f && gz < 10.0f) {
            // Match XLA: div-by-const lowered to mul-by-reciprocal (1/0.4 == 2.5f
            // exactly in fp32). add-then-mul cannot be FMA-contracted.
            const float rx = (gx + 51.2f) * 2.5f;
            const float ry = (gy + 51.2f) * 2.5f;
            int ix = (int)rx;
            int iy = (int)ry;
            ix = min(max(ix, 0), NX - 1);
            iy = min(max(iy, 0), NY - 1);
            flat = ix * NY + iy;
        }
        s_flat[t] = flat;
    }
    __syncthreads();

    // x index: (((b*D+d)*C + c)*H + h)*W + w
    const long long x_base = ((long long)(b * D_DIM + d) * C_DIM * H_DIM + h) * W_DIM;
    const int c_stride = H_DIM * W_DIM;                       // 2816
    float* const sb = g_scratch + (long long)b * QUADS * NCELL * 4;

    const int total = QUADS * W_DIM;     // 20 * 88 = 1760
    for (int idx = t; idx < total; idx += blockDim.x) {
        const int q = idx / W_DIM;       // channel quad 0..19
        const int w = idx - q * W_DIM;
        const int flat = s_flat[w];
        if (flat >= 0) {
            // Evict-first loads: x is streamed once, never reused — keep L2
            // for the scratch RMW working set.
            const float* xp = x + x_base + (long long)(q * 4) * c_stride + w;
            float v0 = __ldcs(xp);
            float v1 = __ldcs(xp + c_stride);
            float v2 = __ldcs(xp + 2 * c_stride);
            float v3 = __ldcs(xp + 3 * c_stride);
            float* dst = sb + ((long long)(q * NCELL + flat) << 2);  // 16B aligned
            asm volatile("red.global.add.v4.f32 [%0], {%1, %2, %3, %4};"
                         :: "l"(dst), "f"(v0), "f"(v1), "f"(v2), "f"(v3)
                         : "memory");
        }
    }
}

// ---------------------------------------------------------------------------
// Reshape + zero: scratch (B, QUADS, NCELL, 4) -> out (B, C, NCELL).
// Thread handles one quad (b, q, cell): one coalesced float4 load, four
// warp-coalesced scalar stores (cells map to lanes), one float4 zero-store.
// No shared memory, no transpose tile. Unroll-4 grid-stride for MLP.
// Output stores use streaming hint so the zeroed scratch lines stay in L2
// for the next replay's scatter.
// ---------------------------------------------------------------------------
__global__ void __launch_bounds__(256) reshape_zero_kernel(float* __restrict__ out)
{
    const long long NQ = (long long)B_DIM * QUADS * NCELL;   // 10,485,760 quads
    float4* const sc = (float4*)g_scratch;

    long long i0 = (long long)blockIdx.x * (blockDim.x * 4) + threadIdx.x;
    const long long stride = (long long)gridDim.x * blockDim.x * 4;

    for (long long base = i0; base < NQ; base += stride) {
        #pragma unroll
        for (int u = 0; u < 4; u++) {
            const long long i = base + (long long)u * 256;
            if (i < NQ) {
                const int cell = (int)(i & (NCELL - 1));
                const int bq   = (int)(i >> 16);          // b*20 + q
                const int b    = bq / QUADS;
                const int q    = bq - b * QUADS;

                float4 v = sc[i];
                sc[i] = make_float4(0.f, 0.f, 0.f, 0.f);

                float* ob = out + ((long long)(b * C_DIM + q * 4) << 16) + cell;
                __stcs(ob,                v.x);
                __stcs(ob + (1LL << 16),  v.y);
                __stcs(ob + (2LL << 16),  v.z);
                __stcs(ob + (3LL << 16),  v.w);
            }
        }
    }
}

extern "C" void kernel_launch(void* const* d_in, const int* in_sizes, int n_in,
                              void* d_out, int out_size) {
    const float* geom = (const float*)d_in[0];   // (8,40,32,88,3)
    const float* x    = (const float*)d_in[1];   // (8,40,80,32,88)
    float* out        = (float*)d_out;           // (8,80,256,256)

    // Scratch is zero here: .bss zero-init on first call; reshape_zero_kernel
    // restores it to zero on every call thereafter.
    scatter_kernel<<<B_DIM * D_DIM * H_DIM, 256>>>(geom, x);

    // 10,485,760 quads / (256 threads * 4 per thread) = 10240 blocks
    reshape_zero_kernel<<<10240, 256>>>(out);
}

// round 6
// speedup vs baseline: 2.6356x; 2.6356x over previous
#include <cuda_runtime.h>

// Problem constants
#define B_DIM 8
#define D_DIM 40
#define H_DIM 32
#define W_DIM 88
#define C_DIM 80
#define C_PASS 40                 // channels per pass
#define QUADS_P (C_PASS / 4)      // 10 quads per pass
#define NX 256
#define NY 256
#define NCELL (NX * NY)           // 65536 cells per batch
// NZ = 1

// Scratch for ONE channel-pass: (B, NCELL, C_PASS) fp32 = 84 MB -> L2-resident.
__device__ float g_scratch[(long long)B_DIM * NCELL * C_PASS];

// ---------------------------------------------------------------------------
// Zero scratch (84 MB). Pure store kernel — writes land in L2 (write-back)
// and stay there for the scatter.
// ---------------------------------------------------------------------------
__global__ void __launch_bounds__(256) zero_scratch_kernel() {
    float4* const sc = (float4*)g_scratch;
    const int N4 = (B_DIM * NCELL * C_PASS) / 4;   // 5,242,880
    int i = blockIdx.x * (256 * 4) + threadIdx.x;
    #pragma unroll
    for (int u = 0; u < 4; u++) {
        sc[i + u * 256] = make_float4(0.f, 0.f, 0.f, 0.f);
    }
    (void)N4;
}

// ---------------------------------------------------------------------------
// Scatter for one channel-pass: one block per (b, d, h) row of W=88 points.
// Phase 1: threads 0..87 compute the flat cell index (or -1) into smem.
// Phase 2: loop over (quad q=0..9, w): 4 evict-first coalesced x loads, one
//          red.global.add.v4.f32 into L2-resident scratch[b][flat][4q..4q+3].
// ---------------------------------------------------------------------------
__global__ void __launch_bounds__(256) scatter_kernel(
    const float* __restrict__ geom,   // (B, D, H, W, 3)
    const float* __restrict__ x,      // (B, D, C, H, W)
    int c0)                           // channel offset of this pass (0 or 40)
{
    __shared__ int s_flat[W_DIM];

    const int bid = blockIdx.x;           // 0 .. B*D*H-1
    const int h   = bid % H_DIM;
    const int bd  = bid / H_DIM;
    const int d   = bd % D_DIM;
    const int b   = bd / D_DIM;

    const int t = threadIdx.x;

    if (t < W_DIM) {
        const float* g = geom + ((long long)bid * W_DIM + t) * 3;
        const float gx = g[0];
        const float gy = g[1];
        const float gz = g[2];

        int flat = -1;
        if (gx >= -51.2f && gx < 51.2f &&
            gy >= -51.2f && gy < 51.2f &&
            gz >= -10.0f && gz < 10.0f) {
            // Match XLA: div-by-const lowered to mul-by-reciprocal (1/0.4 == 2.5f
            // exactly in fp32). add-then-mul cannot be FMA-contracted.
            const float rx = (gx + 51.2f) * 2.5f;
            const float ry = (gy + 51.2f) * 2.5f;
            int ix = (int)rx;
            int iy = (int)ry;
            ix = min(max(ix, 0), NX - 1);
            iy = min(max(iy, 0), NY - 1);
            flat = ix * NY + iy;
        }
        s_flat[t] = flat;
    }
    __syncthreads();

    // x index: (((b*D+d)*C + c0+c)*H + h)*W + w
    const long long x_base =
        ((long long)((b * D_DIM + d) * C_DIM + c0) * H_DIM + h) * W_DIM;
    const int c_stride = H_DIM * W_DIM;                       // 2816
    float* const sb = g_scratch + (long long)b * NCELL * C_PASS;

    const int total = QUADS_P * W_DIM;   // 10 * 88 = 880
    for (int idx = t; idx < total; idx += blockDim.x) {
        const int q = idx / W_DIM;       // quad 0..9
        const int w = idx - q * W_DIM;
        const int flat = s_flat[w];
        if (flat >= 0) {
            // Evict-first: x is streamed once — keep L2 for the scratch RMWs.
            const float* xp = x + x_base + (long long)(q * 4) * c_stride + w;
            float v0 = __ldcs(xp);
            float v1 = __ldcs(xp + c_stride);
            float v2 = __ldcs(xp + 2 * c_stride);
            float v3 = __ldcs(xp + 3 * c_stride);
            float* dst = sb + (long long)flat * C_PASS + q * 4;  // 16B aligned
            asm volatile("red.global.add.v4.f32 [%0], {%1, %2, %3, %4};"
                         :: "l"(dst), "f"(v0), "f"(v1), "f"(v2), "f"(v3)
                         : "memory");
        }
    }
}

// ---------------------------------------------------------------------------
// Pure transpose: scratch (B, NCELL, C_PASS) -> out (B, C, NCELL) slab for
// this pass. 128 cells x 40 channels per block via smem tile; float4
// coalesced on both sides. Reads hit L2; only output stores go to DRAM.
// ---------------------------------------------------------------------------
__global__ void __launch_bounds__(256) transpose_kernel(
    float* __restrict__ out, int c0)
{
    __shared__ float tile[128][41];   // 41-pad: conflict-reduced

    const int blk     = blockIdx.x;            // 0 .. B*512-1
    const int b       = blk >> 9;
    const int tile0   = (blk & 511) * 128;     // first cell of tile
    const int t       = threadIdx.x;

    const float4* src = (const float4*)(g_scratch +
                        ((long long)b * NCELL + tile0) * C_PASS);

    // Load: 128 cells * 10 float4 = 1280 vec loads, coalesced (L2 hits).
    #pragma unroll
    for (int i = t; i < 128 * 10; i += 256) {
        const int cell = i / 10;
        const int q    = i - cell * 10;
        float4 v = src[i];
        tile[cell][q * 4 + 0] = v.x;
        tile[cell][q * 4 + 1] = v.y;
        tile[cell][q * 4 + 2] = v.z;
        tile[cell][q * 4 + 3] = v.w;
    }
    __syncthreads();

    // Store: 40 channels * 32 cell-quads = 1280 float4 stores, coalesced.
    float* ob = out + ((long long)b * C_DIM + c0) * NCELL + tile0;
    #pragma unroll
    for (int i = t; i < 40 * 32; i += 256) {
        const int c  = i / 32;
        const int cg = i - c * 32;
        float4 v;
        v.x = tile[cg * 4 + 0][c];
        v.y = tile[cg * 4 + 1][c];
        v.z = tile[cg * 4 + 2][c];
        v.w = tile[cg * 4 + 3][c];
        __stcs((float4*)(ob + (long long)c * NCELL + cg * 4), v);
    }
}

extern "C" void kernel_launch(void* const* d_in, const int* in_sizes, int n_in,
                              void* d_out, int out_size) {
    const float* geom = (const float*)d_in[0];   // (8,40,32,88,3)
    const float* x    = (const float*)d_in[1];   // (8,40,80,32,88)
    float* out        = (float*)d_out;           // (8,80,256,256)

    const int zero_blocks = (B_DIM * NCELL * C_PASS / 4) / (256 * 4); // 5120
    const int scat_blocks = B_DIM * D_DIM * H_DIM;                    // 10240
    const int tr_blocks   = B_DIM * (NCELL / 128);                    // 4096

    for (int pass = 0; pass < 2; pass++) {
        const int c0 = pass * C_PASS;
        zero_scratch_kernel<<<zero_blocks, 256>>>();
        scatter_kernel<<<scat_blocks, 256>>>(geom, x, c0);
        transpose_kernel<<<tr_blocks, 256>>>(out, c0);
    }
}

// round 7
// speedup vs baseline: 2.8557x; 1.0835x over previous
#include <cuda_runtime.h>

// Problem constants
#define B_DIM 8
#define D_DIM 40
#define H_DIM 32
#define W_DIM 88
#define C_DIM 80
#define QUADS (C_DIM / 4)
#define NX 256
#define NY 256
#define NCELL (NX * NY)                     // 65536 cells per batch
#define NPTS (B_DIM * D_DIM * H_DIM * W_DIM) // 901120 points
#define NROWS (B_DIM * D_DIM * H_DIM)        // 10240 rows of 88
// NZ = 1

// Scratch accumulator (cell-major): (B, NCELL, C) fp32 = 168 MB. .bss zero.
__device__ float g_scratch[(long long)B_DIM * NCELL * C_DIM];
// Per-(b,cell) contributor count: 2 MB.
__device__ int g_count[B_DIM * NCELL];
// Cached flat cell index per point (-1 = out of bounds): 3.6 MB.
__device__ int g_flat[NPTS];

// ---------------------------------------------------------------------------
// Zero scratch + count table (pure stores).
// 10,485,760 scratch float4 + 131,072 count int4 = 10,616,832 vec stores.
// ---------------------------------------------------------------------------
#define N4_SCRATCH ((B_DIM * NCELL * C_DIM) / 4)
#define N4_TOTAL   (N4_SCRATCH + (B_DIM * NCELL) / 4)
__global__ void __launch_bounds__(256) zero_kernel() {
    float4* const sc = (float4*)g_scratch;
    int4*   const ct = (int4*)g_count;
    int i = blockIdx.x * (256 * 4) + threadIdx.x;
    #pragma unroll
    for (int u = 0; u < 4; u++) {
        const int j = i + u * 256;
        if (j < N4_SCRATCH) {
            sc[j] = make_float4(0.f, 0.f, 0.f, 0.f);
        } else if (j < N4_TOTAL) {
            ct[j - N4_SCRATCH] = make_int4(0, 0, 0, 0);
        }
    }
}

// ---------------------------------------------------------------------------
// Count pass: one thread per point. Computes the cell index (cached into
// g_flat) and bumps the per-(b,cell) contributor count.
// ---------------------------------------------------------------------------
__global__ void __launch_bounds__(256) count_kernel(
    const float* __restrict__ geom)   // (B, D, H, W, 3)
{
    const int n = blockIdx.x * 256 + threadIdx.x;   // 0 .. NPTS-1 (exact grid)
    const float* g = geom + (long long)n * 3;
    const float gx = g[0];
    const float gy = g[1];
    const float gz = g[2];

    int flat = -1;
    if (gx >= -51.2f && gx < 51.2f &&
        gy >= -51.2f && gy < 51.2f &&
        gz >= -10.0f && gz < 10.0f) {
        // Match XLA: div-by-const lowered to mul-by-reciprocal (1/0.4 == 2.5f
        // exactly in fp32). add-then-mul cannot be FMA-contracted.
        const float rx = (gx + 51.2f) * 2.5f;
        const float ry = (gy + 51.2f) * 2.5f;
        int ix = (int)rx;
        int iy = (int)ry;
        ix = min(max(ix, 0), NX - 1);
        iy = min(max(iy, 0), NY - 1);
        flat = ix * NY + iy;
    }
    g_flat[n] = flat;
    if (flat >= 0) {
        const int b = n / (D_DIM * H_DIM * W_DIM);
        atomicAdd(&g_count[b * NCELL + flat], 1);   // RED (no return)
    }
}

// ---------------------------------------------------------------------------
// Scatter: one block per (b, d, h) row of W=88 points.
// Phase 1: threads 0..87 load the cached cell index + contributor count.
// Phase 2: loop over (quad q, w): 4 evict-first coalesced x loads; if this
//          point is the SOLE contributor to its cell -> plain STG.128 (no
//          LTS atomic slot); otherwise red.global.add.v4.f32.
// ---------------------------------------------------------------------------
__global__ void __launch_bounds__(256) scatter_kernel(
    const float* __restrict__ x)      // (B, D, C, H, W)
{
    __shared__ int s_flat[W_DIM];
    __shared__ int s_cnt[W_DIM];

    const int bid = blockIdx.x;           // 0 .. NROWS-1
    const int h   = bid % H_DIM;
    const int bd  = bid / H_DIM;
    const int d   = bd % D_DIM;
    const int b   = bd / D_DIM;

    const int t = threadIdx.x;

    if (t < W_DIM) {
        const int flat = g_flat[bid * W_DIM + t];
        s_flat[t] = flat;
        s_cnt[t]  = (flat >= 0) ? __ldg(&g_count[b * NCELL + flat]) : 0;
    }
    __syncthreads();

    // x index: (((b*D+d)*C + c)*H + h)*W + w
    const long long x_base = ((long long)(b * D_DIM + d) * C_DIM * H_DIM + h) * W_DIM;
    const int c_stride = H_DIM * W_DIM;                       // 2816
    float* const sb = g_scratch + (long long)b * NCELL * C_DIM;

    const int total = QUADS * W_DIM;     // 20 * 88 = 1760
    for (int idx = t; idx < total; idx += blockDim.x) {
        const int q = idx / W_DIM;       // channel quad 0..19
        const int w = idx - q * W_DIM;
        const int flat = s_flat[w];
        if (flat >= 0) {
            // Evict-first: x is streamed once — keep L2 for the RMW set.
            const float* xp = x + x_base + (long long)(q * 4) * c_stride + w;
            float v0 = __ldcs(xp);
            float v1 = __ldcs(xp + c_stride);
            float v2 = __ldcs(xp + 2 * c_stride);
            float v3 = __ldcs(xp + 3 * c_stride);
            float* dst = sb + (long long)flat * C_DIM + q * 4;  // 16B aligned
            if (s_cnt[w] == 1) {
                // Sole contributor to this (b,cell): exact without an atomic.
                *(float4*)dst = make_float4(v0, v1, v2, v3);
            } else {
                asm volatile("red.global.add.v4.f32 [%0], {%1, %2, %3, %4};"
                             :: "l"(dst), "f"(v0), "f"(v1), "f"(v2), "f"(v3)
                             : "memory");
            }
        }
    }
}

// ---------------------------------------------------------------------------
// Pure transpose: scratch (B, NCELL, C) -> out (B, C, NCELL).
// 128 cells x 80 channels per block via smem tile; float4 coalesced on both
// sides. Streaming hints: scratch is read once, out is written once.
// ---------------------------------------------------------------------------
__global__ void __launch_bounds__(256) transpose_kernel(float* __restrict__ out)
{
    __shared__ float tile[128][81];

    const int blk   = blockIdx.x;            // 0 .. B*512-1
    const int b     = blk >> 9;
    const int tile0 = (blk & 511) * 128;     // first cell of tile
    const int t     = threadIdx.x;

    const float4* src = (const float4*)(g_scratch +
                        ((long long)b * NCELL + tile0) * C_DIM);

    // Load: 128 cells * 20 float4 = 2560 vec loads, coalesced.
    #pragma unroll
    for (int i = t; i < 128 * 20; i += 256) {
        const int cell = i / 20;
        const int q    = i - cell * 20;
        float4 v = __ldcs(&src[i]);
        tile[cell][q * 4 + 0] = v.x;
        tile[cell][q * 4 + 1] = v.y;
        tile[cell][q * 4 + 2] = v.z;
        tile[cell][q * 4 + 3] = v.w;
    }
    __syncthreads();

    // Store: 80 channels * 32 cell-quads = 2560 float4 stores, coalesced.
    float* ob = out + (long long)b * C_DIM * NCELL + tile0;
    #pragma unroll
    for (int i = t; i < 80 * 32; i += 256) {
        const int c  = i / 32;
        const int cg = i - c * 32;
        float4 v;
        v.x = tile[cg * 4 + 0][c];
        v.y = tile[cg * 4 + 1][c];
        v.z = tile[cg * 4 + 2][c];
        v.w = tile[cg * 4 + 3][c];
        __stcs((float4*)(ob + (long long)c * NCELL + cg * 4), v);
    }
}

extern "C" void kernel_launch(void* const* d_in, const int* in_sizes, int n_in,
                              void* d_out, int out_size) {
    const float* geom = (const float*)d_in[0];   // (8,40,32,88,3)
    const float* x    = (const float*)d_in[1];   // (8,40,80,32,88)
    float* out        = (float*)d_out;           // (8,80,256,256)

    // 10,616,832 vec4 stores / (256 threads * 4) = 10368 blocks exactly.
    zero_kernel<<<10368, 256>>>();
    // 901120 points / 256 = 3520 blocks exactly.
    count_kernel<<<3520, 256>>>(geom);
    scatter_kernel<<<NROWS, 256>>>(x);
    transpose_kernel<<<B_DIM * (NCELL / 128), 256>>>(out);
}

// round 8
// speedup vs baseline: 2.8941x; 1.0134x over previous
#include <cuda_runtime.h>

// Problem constants
#define B_DIM 8
#define D_DIM 40
#define H_DIM 32
#define W_DIM 88
#define C_DIM 80
#define QUADS (C_DIM / 4)
#define NX 256
#define NY 256
#define NCELL (NX * NY)                      // 65536 cells per batch
#define NPTS (B_DIM * D_DIM * H_DIM * W_DIM) // 901120 points
#define NROWS (B_DIM * D_DIM * H_DIM)        // 10240 rows of 88
// NZ = 1

// Scratch accumulator (cell-major): (B, NCELL, C) fp32 = 168 MB. .bss zero.
__device__ float g_scratch[(long long)B_DIM * NCELL * C_DIM];
// Per-(b,cell) contributor count: 2 MB.
__device__ int g_count[B_DIM * NCELL];
// Cached flat cell index per point (-1 = out of bounds): 3.6 MB.
__device__ int g_flat[NPTS];

// ---------------------------------------------------------------------------
// Reset the count table (2 MB -> 131072 int4).
// ---------------------------------------------------------------------------
__global__ void __launch_bounds__(256) zero_count_kernel() {
    int4* const ct = (int4*)g_count;
    const int i = blockIdx.x * 256 + threadIdx.x;   // grid sized exactly
    ct[i] = make_int4(0, 0, 0, 0);
}

// ---------------------------------------------------------------------------
// Count pass: one thread per point. Computes the cell index (cached into
// g_flat) and bumps the per-(b,cell) contributor count.
// ---------------------------------------------------------------------------
__global__ void __launch_bounds__(256) count_kernel(
    const float* __restrict__ geom)   // (B, D, H, W, 3)
{
    const int n = blockIdx.x * 256 + threadIdx.x;   // 0 .. NPTS-1 (exact grid)
    const float* g = geom + (long long)n * 3;
    const float gx = g[0];
    const float gy = g[1];
    const float gz = g[2];

    int flat = -1;
    if (gx >= -51.2f && gx < 51.2f &&
        gy >= -51.2f && gy < 51.2f &&
        gz >= -10.0f && gz < 10.0f) {
        // Match XLA: div-by-const lowered to mul-by-reciprocal (1/0.4 == 2.5f
        // exactly in fp32). add-then-mul cannot be FMA-contracted.
        const float rx = (gx + 51.2f) * 2.5f;
        const float ry = (gy + 51.2f) * 2.5f;
        int ix = (int)rx;
        int iy = (int)ry;
        ix = min(max(ix, 0), NX - 1);
        iy = min(max(iy, 0), NY - 1);
        flat = ix * NY + iy;
    }
    g_flat[n] = flat;
    if (flat >= 0) {
        const int b = n / (D_DIM * H_DIM * W_DIM);
        atomicAdd(&g_count[b * NCELL + flat], 1);   // RED (no return)
    }
}

// ---------------------------------------------------------------------------
// Selective zero: only cells with count >= 2 need a zero base (count==1 is
// fully overwritten by the sole-store; count==0 never read by transpose).
// One thread per float4 slot; ~28% of cells qualify -> ~47 MB of writes.
// ---------------------------------------------------------------------------
__global__ void __launch_bounds__(256) zero_scratch_kernel() {
    float4* const sc = (float4*)g_scratch;
    const int i0 = blockIdx.x * (256 * 4) + threadIdx.x;
    #pragma unroll
    for (int u = 0; u < 4; u++) {
        const int i = i0 + u * 256;            // float4 slot, grid exact
        const int cell = i / QUADS;            // (b*NCELL + cell) combined
        if (__ldg(&g_count[cell]) >= 2) {
            sc[i] = make_float4(0.f, 0.f, 0.f, 0.f);
        }
    }
}

// ---------------------------------------------------------------------------
// Scatter: one block per (b, d, h) row of W=88 points.
// Phase 1: threads 0..87 load the cached cell index + contributor count.
// Phase 2: loop over (quad q, w): 4 evict-first coalesced x loads; sole
//          contributor -> plain STG.128 (no LTS atomic slot); otherwise
//          red.global.add.v4.f32.
// ---------------------------------------------------------------------------
__global__ void __launch_bounds__(256) scatter_kernel(
    const float* __restrict__ x)      // (B, D, C, H, W)
{
    __shared__ int s_flat[W_DIM];
    __shared__ int s_cnt[W_DIM];

    const int bid = blockIdx.x;           // 0 .. NROWS-1
    const int h   = bid % H_DIM;
    const int bd  = bid / H_DIM;
    const int d   = bd % D_DIM;
    const int b   = bd / D_DIM;

    const int t = threadIdx.x;

    if (t < W_DIM) {
        const int flat = g_flat[bid * W_DIM + t];
        s_flat[t] = flat;
        s_cnt[t]  = (flat >= 0) ? __ldg(&g_count[b * NCELL + flat]) : 0;
    }
    __syncthreads();

    // x index: (((b*D+d)*C + c)*H + h)*W + w
    const long long x_base = ((long long)(b * D_DIM + d) * C_DIM * H_DIM + h) * W_DIM;
    const int c_stride = H_DIM * W_DIM;                       // 2816
    float* const sb = g_scratch + (long long)b * NCELL * C_DIM;

    const int total = QUADS * W_DIM;     // 20 * 88 = 1760
    for (int idx = t; idx < total; idx += blockDim.x) {
        const int q = idx / W_DIM;       // channel quad 0..19
        const int w = idx - q * W_DIM;
        const int flat = s_flat[w];
        if (flat >= 0) {
            // Evict-first: x is streamed once — keep L2 for the RMW set.
            const float* xp = x + x_base + (long long)(q * 4) * c_stride + w;
            float v0 = __ldcs(xp);
            float v1 = __ldcs(xp + c_stride);
            float v2 = __ldcs(xp + 2 * c_stride);
            float v3 = __ldcs(xp + 3 * c_stride);
            float* dst = sb + (long long)flat * C_DIM + q * 4;  // 16B aligned
            if (s_cnt[w] == 1) {
                // Sole contributor: exact without an atomic (overwrites any
                // stale data, which is why count==1 cells need no zeroing).
                *(float4*)dst = make_float4(v0, v1, v2, v3);
            } else {
                asm volatile("red.global.add.v4.f32 [%0], {%1, %2, %3, %4};"
                             :: "l"(dst), "f"(v0), "f"(v1), "f"(v2), "f"(v3)
                             : "memory");
            }
        }
    }
}

// ---------------------------------------------------------------------------
// Count-aware transpose: scratch (B, NCELL, C) -> out (B, C, NCELL).
// 64 cells x 80 channels per block. count==0 cells are synthesized as zeros
// (no scratch read). Store phase uses conflict-free scalar LDS (lane stride
// 81 == 17 mod 32) + perfectly coalesced STG.32 (32 consecutive cells).
// ---------------------------------------------------------------------------
__global__ void __launch_bounds__(256) transpose_kernel(float* __restrict__ out)
{
    __shared__ float tile[64][81];   // scalar access, odd-ish stride
    __shared__ int s_cnt[64];

    const int blk   = blockIdx.x;            // 0 .. B*1024-1
    const int b     = blk >> 10;
    const int tile0 = (blk & 1023) * 64;     // first cell of tile
    const int t     = threadIdx.x;

    if (t < 64) s_cnt[t] = __ldg(&g_count[b * NCELL + tile0 + t]);
    __syncthreads();

    const float4* src = (const float4*)(g_scratch +
                        ((long long)b * NCELL + tile0) * C_DIM);

    // Load: 64 cells * 20 float4; skip the global read for empty cells.
    #pragma unroll
    for (int i = t; i < 64 * 20; i += 256) {
        const int cell = i / 20;
        const int q    = i - cell * 20;
        float4 v = make_float4(0.f, 0.f, 0.f, 0.f);
        if (s_cnt[cell] > 0) v = __ldcs(&src[i]);
        tile[cell][q * 4 + 0] = v.x;
        tile[cell][q * 4 + 1] = v.y;
        tile[cell][q * 4 + 2] = v.z;
        tile[cell][q * 4 + 3] = v.w;
    }
    __syncthreads();

    // Store: 80 channels * 64 cells, scalar. Lanes cover 32 consecutive
    // cells of one channel: LDS conflict-free, STG.32 fully coalesced.
    float* ob = out + (long long)b * C_DIM * NCELL + tile0;
    #pragma unroll
    for (int i = t; i < 80 * 64; i += 256) {
        const int c    = i >> 6;       // / 64
        const int cell = i & 63;
        __stcs(ob + (long long)c * NCELL + cell, tile[cell][c]);
    }
}

extern "C" void kernel_launch(void* const* d_in, const int* in_sizes, int n_in,
                              void* d_out, int out_size) {
    const float* geom = (const float*)d_in[0];   // (8,40,32,88,3)
    const float* x    = (const float*)d_in[1];   // (8,40,80,32,88)
    float* out        = (float*)d_out;           // (8,80,256,256)

    // 131072 ints -> 32768 int4 / 256 = 128 blocks exactly.
    zero_count_kernel<<<128, 256>>>();
    // 901120 points / 256 = 3520 blocks exactly.
    count_kernel<<<3520, 256>>>(geom);
    // 10,485,760 float4 slots / (256*4) = 10240 blocks exactly.
    zero_scratch_kernel<<<10240, 256>>>();
    scatter_kernel<<<NROWS, 256>>>(x);
    transpose_kernel<<<B_DIM * (NCELL / 64), 256>>>(out);
}